// round 1
// baseline (speedup 1.0000x reference)
#include <cuda_runtime.h>
#include <cuda_bf16.h>
#include <cstdint>

#define E_DIM 256
#define MQ (64*8*128)     /* 65536 query tokens  */
#define MC (2*MQ)         /* 131072 constant rows */

// ---------------- scratch (allocation-free: __device__ globals) ----------------
__device__ float g_Q [(size_t)MQ*E_DIM];
__device__ float g_K [(size_t)MC*E_DIM];
__device__ float g_V [(size_t)MC*E_DIM];
__device__ float g_WS[(size_t)MQ*E_DIM];
__device__ __nv_bfloat16 g_Wh[4][E_DIM*E_DIM];
__device__ __nv_bfloat16 g_Wl[4][E_DIM*E_DIM];

// Swizzled smem offset (bf16 elements). Tile is [128 rows][32 cols], row = 64B.
// 16B groups XOR-swizzled by ((row>>1)&3) -> conflict-free ldmatrix & STS.
__device__ __forceinline__ int sw_off(int row, int col){
  return row*32 + (((((col>>3) ^ ((row>>1)&3))) << 3) | (col & 7));
}

__device__ __forceinline__ void ldm4(uint32_t addr, uint32_t r[4]){
  asm volatile("ldmatrix.sync.aligned.m8n8.x4.shared.b16 {%0,%1,%2,%3}, [%4];\n"
    : "=r"(r[0]),"=r"(r[1]),"=r"(r[2]),"=r"(r[3]) : "r"(addr));
}

__device__ __forceinline__ void ldfrag(const __nv_bfloat16* s, int rbase, int ks,
                                       int lane, uint32_t r[4]){
  int row = rbase + (lane & 7) + ((lane & 8) ? 8 : 0);
  int col = ks + ((lane & 16) ? 8 : 0);
  uint32_t a = (uint32_t)__cvta_generic_to_shared(s + sw_off(row, col));
  ldm4(a, r);
}

__device__ __forceinline__ void mma16816(float c[4], const uint32_t a[4],
                                         uint32_t b0, uint32_t b1){
  asm volatile("mma.sync.aligned.m16n8k16.row.col.f32.bf16.bf16.f32 "
    "{%0,%1,%2,%3}, {%4,%5,%6,%7}, {%8,%9}, {%0,%1,%2,%3};\n"
    : "+f"(c[0]),"+f"(c[1]),"+f"(c[2]),"+f"(c[3])
    : "r"(a[0]),"r"(a[1]),"r"(a[2]),"r"(a[3]), "r"(b0),"r"(b1));
}

// ---------------- weight hi/lo split prep ----------------
__global__ void prep_weights(const float* __restrict__ Wq, const float* __restrict__ Wk,
                             const float* __restrict__ Wv, const float* __restrict__ Wo){
  int i = blockIdx.x * blockDim.x + threadIdx.x;   // 0 .. 65535
  const float* src[4] = {Wq, Wk, Wv, Wo};
#pragma unroll
  for (int w = 0; w < 4; w++){
    float v = src[w][i];
    __nv_bfloat16 h = __float2bfloat16(v);
    g_Wh[w][i] = h;
    g_Wl[w][i] = __float2bfloat16(v - __bfloat162float(h));
  }
}

// ---------------- GEMM: Y[M,256] = X[M,256] @ W[256,256]^T + bias ----------------
// split-bf16: acc += Ahi*Bhi + Alo*Bhi + Ahi*Blo  (full ~fp32 accuracy)
// CTA tile 128x128, BK=32, 8 warps (wm 0..3 x wn 0..1), warp tile 32x64.
__global__ void __launch_bounds__(256, 1)
gemm_split(const float* __restrict__ Xext, int xsel, int widx,
           const float* __restrict__ bias, float* __restrict__ Yext, int ysel)
{
  __shared__ __nv_bfloat16 sAh[128*32];
  __shared__ __nv_bfloat16 sAl[128*32];
  __shared__ __nv_bfloat16 sBh[128*32];
  __shared__ __nv_bfloat16 sBl[128*32];

  const float* __restrict__ X = xsel ? g_WS : Xext;
  float* __restrict__ Y = (ysel==0) ? g_Q : (ysel==1) ? g_K : (ysel==2) ? g_V : Yext;
  const __nv_bfloat16* __restrict__ Wh = g_Wh[widx];
  const __nv_bfloat16* __restrict__ Wl = g_Wl[widx];

  const int tid  = threadIdx.x;
  const int lane = tid & 31;
  const int warp = tid >> 5;
  const int wm   = warp & 3;        // M warp (0..3) -> rows wm*32
  const int wn   = warp >> 2;       // N warp (0..1) -> cols wn*64
  const size_t mBase = (size_t)blockIdx.y * 128;
  const int    nBase = blockIdx.x * 128;
  const int lrow = tid >> 3;        // 0..31
  const int lkq  = tid & 7;         // float4 index within 32-wide row

  float4 ra[4];
  uint2  rbh[4], rbl[4];

  float acc[2][8][4];
#pragma unroll
  for (int i=0;i<2;i++)
#pragma unroll
    for (int j=0;j<8;j++)
#pragma unroll
      for (int k=0;k<4;k++) acc[i][j][k] = 0.f;

  auto loadG = [&](int kk){
#pragma unroll
    for (int i=0;i<4;i++){
      int row = lrow + 32*i;
      ra[i] = *reinterpret_cast<const float4*>(X + (mBase+row)*E_DIM + kk + lkq*4);
      size_t woff = (size_t)(nBase+row)*E_DIM + kk + lkq*4;
      rbh[i] = *reinterpret_cast<const uint2*>(Wh + woff);
      rbl[i] = *reinterpret_cast<const uint2*>(Wl + woff);
    }
  };

  auto stS = [&](){
#pragma unroll
    for (int i=0;i<4;i++){
      int row = lrow + 32*i;
      float v[4] = {ra[i].x, ra[i].y, ra[i].z, ra[i].w};
#pragma unroll
      for (int j=0;j<2;j++){
        float x0 = v[2*j], x1 = v[2*j+1];
        __nv_bfloat16 h0 = __float2bfloat16(x0);
        __nv_bfloat16 h1 = __float2bfloat16(x1);
        __nv_bfloat162 h2; h2.x = h0; h2.y = h1;
        __nv_bfloat162 l2;
        l2.x = __float2bfloat16(x0 - __bfloat162float(h0));
        l2.y = __float2bfloat16(x1 - __bfloat162float(h1));
        int col = lkq*4 + 2*j;
        *reinterpret_cast<__nv_bfloat162*>(&sAh[sw_off(row,col)]) = h2;
        *reinterpret_cast<__nv_bfloat162*>(&sAl[sw_off(row,col)]) = l2;
      }
      *reinterpret_cast<uint2*>(&sBh[sw_off(row, lkq*4)]) = rbh[i];
      *reinterpret_cast<uint2*>(&sBl[sw_off(row, lkq*4)]) = rbl[i];
    }
  };

  loadG(0);
  stS();
  __syncthreads();

  for (int kc = 0; kc < 8; kc++){
    if (kc < 7) loadG((kc+1)*32);

#pragma unroll
    for (int ks2 = 0; ks2 < 2; ks2++){
      const int ks = ks2*16;
      uint32_t Ah[2][4], Al[2][4], Bh[4][4], Bl[4][4];
#pragma unroll
      for (int mt=0; mt<2; mt++){
        ldfrag(sAh, wm*32 + mt*16, ks, lane, Ah[mt]);
        ldfrag(sAl, wm*32 + mt*16, ks, lane, Al[mt]);
      }
#pragma unroll
      for (int bt=0; bt<4; bt++){
        ldfrag(sBh, wn*64 + bt*16, ks, lane, Bh[bt]);
        ldfrag(sBl, wn*64 + bt*16, ks, lane, Bl[bt]);
      }
#pragma unroll
      for (int mt=0; mt<2; mt++)
#pragma unroll
        for (int nt=0; nt<8; nt++){
          const int bt = nt >> 1, od = nt & 1;
          float* c = acc[mt][nt];
          mma16816(c, Ah[mt], Bh[bt][od], Bh[bt][2+od]);   // hi*hi
          mma16816(c, Al[mt], Bh[bt][od], Bh[bt][2+od]);   // lo*hi
          mma16816(c, Ah[mt], Bl[bt][od], Bl[bt][2+od]);   // hi*lo
        }
    }

    __syncthreads();
    if (kc < 7){ stS(); __syncthreads(); }
  }

  // epilogue: +bias, fp32 stores
#pragma unroll
  for (int mt=0; mt<2; mt++){
#pragma unroll
    for (int nt=0; nt<8; nt++){
      size_t m = mBase + wm*32 + mt*16 + (lane>>2);
      int    n = nBase + wn*64 + nt*8 + (lane&3)*2;
      float b0 = bias[n], b1 = bias[n+1];
      float2 v0 = make_float2(acc[mt][nt][0] + b0, acc[mt][nt][1] + b1);
      float2 v1 = make_float2(acc[mt][nt][2] + b0, acc[mt][nt][3] + b1);
      *reinterpret_cast<float2*>(Y + m*E_DIM + n)      = v0;
      *reinterpret_cast<float2*>(Y + (m+8)*E_DIM + n)  = v1;
    }
  }
}

// ---------------- attention: warp per token, fp32, 2-key softmax ----------------
__global__ void __launch_bounds__(256)
attn_kernel()
{
  const int gw   = (blockIdx.x * 256 + threadIdx.x) >> 5;  // token id
  const int lane = threadIdx.x & 31;                        // 8 lanes per head

  const float4* q  = reinterpret_cast<const float4*>(g_Q + (size_t)gw*E_DIM);
  const float4* k0 = reinterpret_cast<const float4*>(g_K + (size_t)(2*gw  )*E_DIM);
  const float4* k1 = reinterpret_cast<const float4*>(g_K + (size_t)(2*gw+1)*E_DIM);
  const float4* v0 = reinterpret_cast<const float4*>(g_V + (size_t)(2*gw  )*E_DIM);
  const float4* v1 = reinterpret_cast<const float4*>(g_V + (size_t)(2*gw+1)*E_DIM);
  float4*       ws = reinterpret_cast<float4*>(g_WS + (size_t)gw*E_DIM);

  float4 qa = q[2*lane],  qb = q[2*lane+1];
  float4 k0a = k0[2*lane], k0b = k0[2*lane+1];
  float4 k1a = k1[2*lane], k1b = k1[2*lane+1];

  float s0 = qa.x*k0a.x + qa.y*k0a.y + qa.z*k0a.z + qa.w*k0a.w
           + qb.x*k0b.x + qb.y*k0b.y + qb.z*k0b.z + qb.w*k0b.w;
  float s1 = qa.x*k1a.x + qa.y*k1a.y + qa.z*k1a.z + qa.w*k1a.w
           + qb.x*k1b.x + qb.y*k1b.y + qb.z*k1b.z + qb.w*k1b.w;

#pragma unroll
  for (int off = 4; off > 0; off >>= 1){            // reduce within 8-lane head group
    s0 += __shfl_xor_sync(0xffffffffu, s0, off);
    s1 += __shfl_xor_sync(0xffffffffu, s1, off);
  }
  s0 *= 0.125f;  s1 *= 0.125f;                       // 1/sqrt(D), D=64
  float mx = fmaxf(s0, s1);
  float e0 = __expf(s0 - mx), e1 = __expf(s1 - mx);
  float inv = 1.0f / (e0 + e1);
  float w0 = e0 * inv, w1 = e1 * inv;

  float4 v0a = v0[2*lane], v0b = v0[2*lane+1];
  float4 v1a = v1[2*lane], v1b = v1[2*lane+1];
  float4 oa, ob;
  oa.x = w0*v0a.x + w1*v1a.x;  oa.y = w0*v0a.y + w1*v1a.y;
  oa.z = w0*v0a.z + w1*v1a.z;  oa.w = w0*v0a.w + w1*v1a.w;
  ob.x = w0*v0b.x + w1*v1b.x;  ob.y = w0*v0b.y + w1*v1b.y;
  ob.z = w0*v0b.z + w1*v1b.z;  ob.w = w0*v0b.w + w1*v1b.w;
  ws[2*lane]   = oa;
  ws[2*lane+1] = ob;
}

// ---------------- launch ----------------
extern "C" void kernel_launch(void* const* d_in, const int* in_sizes, int n_in,
                              void* d_out, int out_size)
{
  const float* p  = (const float*)d_in[0];  // (B,S,A,1,E)  -> [65536,256]
  const float* c  = (const float*)d_in[1];  // (B,S,A,2,E)  -> [131072,256]
  const float* Wq = (const float*)d_in[2];
  const float* bq = (const float*)d_in[3];
  const float* Wk = (const float*)d_in[4];
  const float* bk = (const float*)d_in[5];
  const float* Wv = (const float*)d_in[6];
  const float* bv = (const float*)d_in[7];
  const float* Wo = (const float*)d_in[8];
  const float* bo = (const float*)d_in[9];
  float* out = (float*)d_out;

  prep_weights<<<256, 256>>>(Wq, Wk, Wv, Wo);
  gemm_split<<<dim3(2, MQ/128), 256>>>(p, 0, 0, bq, nullptr, 0);  // Q
  gemm_split<<<dim3(2, MC/128), 256>>>(c, 0, 1, bk, nullptr, 1);  // K
  gemm_split<<<dim3(2, MC/128), 256>>>(c, 0, 2, bv, nullptr, 2);  // V
  attn_kernel<<<MQ/8, 256>>>();
  gemm_split<<<dim3(2, MQ/128), 256>>>(nullptr, 1, 3, bo, out, 3); // O
}

// round 3
// speedup vs baseline: 1.1370x; 1.1370x over previous
#include <cuda_runtime.h>
#include <cuda_bf16.h>
#include <cstdint>

#define E_DIM 256
#define MQ (64*8*128)     /* 65536 query tokens  */
#define MC (2*MQ)         /* 131072 constant rows */

// ---------------- scratch (allocation-free: __device__ globals) ----------------
__device__ float g_Q [(size_t)MQ*E_DIM];
__device__ float g_K [(size_t)MC*E_DIM];
__device__ float g_V [(size_t)MC*E_DIM];
__device__ float g_WS[(size_t)MQ*E_DIM];
__device__ __nv_bfloat16 g_Wh[4][E_DIM*E_DIM];
__device__ __nv_bfloat16 g_Wl[4][E_DIM*E_DIM];

// Swizzled smem offset (bf16 elements). Tile is [128 rows][32 cols], row = 64B.
// 16B groups XOR-swizzled by ((row>>1)&3) -> conflict-free ldmatrix & STS.
__device__ __forceinline__ int sw_off(int row, int col){
  return row*32 + (((((col>>3) ^ ((row>>1)&3))) << 3) | (col & 7));
}

__device__ __forceinline__ void ldm4(uint32_t addr, uint32_t r[4]){
  asm volatile("ldmatrix.sync.aligned.m8n8.x4.shared.b16 {%0,%1,%2,%3}, [%4];\n"
    : "=r"(r[0]),"=r"(r[1]),"=r"(r[2]),"=r"(r[3]) : "r"(addr));
}

__device__ __forceinline__ void ldfrag(const __nv_bfloat16* s, int rbase, int ks,
                                       int lane, uint32_t r[4]){
  int row = rbase + (lane & 7) + ((lane & 8) ? 8 : 0);
  int col = ks + ((lane & 16) ? 8 : 0);
  uint32_t a = (uint32_t)__cvta_generic_to_shared(s + sw_off(row, col));
  ldm4(a, r);
}

__device__ __forceinline__ void mma16816(float c[4], const uint32_t a[4],
                                         uint32_t b0, uint32_t b1){
  asm volatile("mma.sync.aligned.m16n8k16.row.col.f32.bf16.bf16.f32 "
    "{%0,%1,%2,%3}, {%4,%5,%6,%7}, {%8,%9}, {%0,%1,%2,%3};\n"
    : "+f"(c[0]),"+f"(c[1]),"+f"(c[2]),"+f"(c[3])
    : "r"(a[0]),"r"(a[1]),"r"(a[2]),"r"(a[3]), "r"(b0),"r"(b1));
}

__device__ __forceinline__ void cp_async16(uint32_t dst, const void* src){
  asm volatile("cp.async.cg.shared.global [%0], [%1], 16;" :: "r"(dst), "l"(src));
}

// ---------------- weight hi/lo split prep ----------------
__global__ void prep_weights(const float* __restrict__ Wq, const float* __restrict__ Wk,
                             const float* __restrict__ Wv, const float* __restrict__ Wo){
  int i = blockIdx.x * blockDim.x + threadIdx.x;   // 0 .. 65535
  const float* src[4] = {Wq, Wk, Wv, Wo};
#pragma unroll
  for (int w = 0; w < 4; w++){
    float v = src[w][i];
    __nv_bfloat16 h = __float2bfloat16(v);
    g_Wh[w][i] = h;
    g_Wl[w][i] = __float2bfloat16(v - __bfloat162float(h));
  }
}

// ---------------- GEMM: Y[M,256] = X[M,256] @ W[256,256]^T + bias ----------------
// split-bf16: acc += Ahi*Bhi + Alo*Bhi + Ahi*Blo.
// CTA tile 128x128, BK=32, 16 warps (wm 0..3 x wn 0..3), warp tile 32x32.
// Double-buffered smem; cp.async for pre-split B; register-staged A convert.
// smem stage: Ah(8K) Al(8K) Bh(8K) Bl(8K) = 32KB; two stages = 64KB dynamic.
#define STAGE_ELEMS (128*32)
#define STAGE_BYTES (4*2*STAGE_ELEMS)
#define SMEM_TOTAL  (2*STAGE_BYTES)

__global__ void __launch_bounds__(512, 1)
gemm_split(const float* __restrict__ Xext, int xsel,
           int wA, int wB, int yA, int yB,
           const float* __restrict__ biasA, const float* __restrict__ biasB,
           float* __restrict__ Yext)
{
  extern __shared__ __align__(128) char smem[];

  const int sel  = (int)(blockIdx.x >> 1);
  const int widx = sel ? wB : wA;
  const int ysel = sel ? yB : yA;
  const float* __restrict__ bias = sel ? biasB : biasA;
  const float* __restrict__ X = xsel ? g_WS : Xext;
  float* __restrict__ Y = (ysel==0)?g_Q : (ysel==1)?g_K : (ysel==2)?g_V : Yext;
  const __nv_bfloat16* __restrict__ Wh = g_Wh[widx];
  const __nv_bfloat16* __restrict__ Wl = g_Wl[widx];

  const int tid  = threadIdx.x;
  const int lane = tid & 31;
  const int warp = tid >> 5;
  const int wm   = warp & 3;        // rows wm*32
  const int wn   = warp >> 2;       // cols wn*32
  const size_t mBase = (size_t)blockIdx.y * 128;
  const int    nBase = (int)(blockIdx.x & 1) * 128;

  // per-stage smem pointers
  __nv_bfloat16* sAh[2]; __nv_bfloat16* sAl[2];
  __nv_bfloat16* sBh[2]; __nv_bfloat16* sBl[2];
#pragma unroll
  for (int s = 0; s < 2; s++){
    char* st = smem + s * STAGE_BYTES;
    sAh[s] = reinterpret_cast<__nv_bfloat16*>(st);
    sAl[s] = reinterpret_cast<__nv_bfloat16*>(st + 8192);
    sBh[s] = reinterpret_cast<__nv_bfloat16*>(st + 16384);
    sBl[s] = reinterpret_cast<__nv_bfloat16*>(st + 24576);
  }

  const float* __restrict__ Xbase = X + mBase * E_DIM;

  // A fill: 1024 float4 slots / 512 threads = 2 each. row = slot>>3 (8 f4/row)
  const int arow0 = tid >> 3,        ac4 = tid & 7;           // slot  t
  const int arow1 = (tid + 512) >> 3;                          // slot  t+512
  // B cp.async: 512 16B chunks: row = t>>2, chunk col = (t&3)*8
  const int brow = tid >> 2, bc8 = (tid & 3) * 8;
  const size_t bgo = (size_t)(nBase + brow) * E_DIM + bc8;

  float4 ra0, ra1;
  auto loadA = [&](int kk){
    ra0 = *reinterpret_cast<const float4*>(Xbase + (size_t)arow0*E_DIM + kk + ac4*4);
    ra1 = *reinterpret_cast<const float4*>(Xbase + (size_t)arow1*E_DIM + kk + ac4*4);
  };
  auto issueB = [&](int kk, int s){
    uint32_t dh = (uint32_t)__cvta_generic_to_shared(&sBh[s][sw_off(brow, bc8)]);
    uint32_t dl = (uint32_t)__cvta_generic_to_shared(&sBl[s][sw_off(brow, bc8)]);
    cp_async16(dh, Wh + bgo + kk);
    cp_async16(dl, Wl + bgo + kk);
    asm volatile("cp.async.commit_group;" ::: "memory");
  };
  auto storeA = [&](int s){
#pragma unroll
    for (int i = 0; i < 2; i++){
      float4 v = i ? ra1 : ra0;
      int row = i ? arow1 : arow0;
      __nv_bfloat162 h0 = __float22bfloat162_rn(make_float2(v.x, v.y));
      __nv_bfloat162 h1 = __float22bfloat162_rn(make_float2(v.z, v.w));
      float2 f0 = __bfloat1622float2(h0), f1 = __bfloat1622float2(h1);
      __nv_bfloat162 l0 = __float22bfloat162_rn(make_float2(v.x - f0.x, v.y - f0.y));
      __nv_bfloat162 l1 = __float22bfloat162_rn(make_float2(v.z - f1.x, v.w - f1.y));
      int o0 = sw_off(row, ac4*4);
      *reinterpret_cast<__nv_bfloat162*>(&sAh[s][o0])   = h0;
      *reinterpret_cast<__nv_bfloat162*>(&sAh[s][o0+2]) = h1;
      *reinterpret_cast<__nv_bfloat162*>(&sAl[s][o0])   = l0;
      *reinterpret_cast<__nv_bfloat162*>(&sAl[s][o0+2]) = l1;
    }
  };

  float acc[2][4][4];
#pragma unroll
  for (int i=0;i<2;i++)
#pragma unroll
    for (int j=0;j<4;j++)
#pragma unroll
      for (int k=0;k<4;k++) acc[i][j][k] = 0.f;

  // prologue: fill stage 0
  issueB(0, 0);
  loadA(0);
  storeA(0);
  asm volatile("cp.async.wait_group 0;" ::: "memory");
  __syncthreads();

  for (int kc = 0; kc < 8; kc++){
    const int cur = kc & 1, nxt = cur ^ 1;
    if (kc < 7){
      issueB((kc+1)*32, nxt);     // async engine starts immediately
      loadA((kc+1)*32);           // global->reg, latency hidden by compute
    }

    // ---- compute on stage cur ----
#pragma unroll
    for (int ks2 = 0; ks2 < 2; ks2++){
      const int ks = ks2*16;
      uint32_t Ah[2][4], Al[2][4], Bh[2][4], Bl[2][4];
#pragma unroll
      for (int mt=0; mt<2; mt++){
        ldfrag(sAh[cur], wm*32 + mt*16, ks, lane, Ah[mt]);
        ldfrag(sAl[cur], wm*32 + mt*16, ks, lane, Al[mt]);
      }
#pragma unroll
      for (int bt=0; bt<2; bt++){
        ldfrag(sBh[cur], wn*32 + bt*16, ks, lane, Bh[bt]);
        ldfrag(sBl[cur], wn*32 + bt*16, ks, lane, Bl[bt]);
      }
#pragma unroll
      for (int mt=0; mt<2; mt++)
#pragma unroll
        for (int nt=0; nt<4; nt++){
          const int bt = nt >> 1, od = nt & 1;
          float* c = acc[mt][nt];
          mma16816(c, Ah[mt], Bh[bt][od], Bh[bt][2+od]);   // hi*hi
          mma16816(c, Al[mt], Bh[bt][od], Bh[bt][2+od]);   // lo*hi
          mma16816(c, Ah[mt], Bl[bt][od], Bl[bt][2+od]);   // hi*lo
        }
    }

    if (kc < 7){
      storeA(nxt);                                  // convert + STS into next stage
      asm volatile("cp.async.wait_group 0;" ::: "memory");
    }
    __syncthreads();
  }

  // epilogue: +bias, fp32 stores
#pragma unroll
  for (int mt=0; mt<2; mt++){
#pragma unroll
    for (int nt=0; nt<4; nt++){
      size_t m = mBase + wm*32 + mt*16 + (lane>>2);
      int    n = nBase + wn*32 + nt*8 + (lane&3)*2;
      float b0 = bias[n], b1 = bias[n+1];
      float2 v0 = make_float2(acc[mt][nt][0] + b0, acc[mt][nt][1] + b1);
      float2 v1 = make_float2(acc[mt][nt][2] + b0, acc[mt][nt][3] + b1);
      *reinterpret_cast<float2*>(Y + m*E_DIM + n)      = v0;
      *reinterpret_cast<float2*>(Y + (m+8)*E_DIM + n)  = v1;
    }
  }
}

// ---------------- attention: warp per token, fp32, 2-key softmax ----------------
__global__ void __launch_bounds__(256)
attn_kernel()
{
  const int gw   = (blockIdx.x * 256 + threadIdx.x) >> 5;  // token id
  const int lane = threadIdx.x & 31;                        // 8 lanes per head

  const float4* q  = reinterpret_cast<const float4*>(g_Q + (size_t)gw*E_DIM);
  const float4* k0 = reinterpret_cast<const float4*>(g_K + (size_t)(2*gw  )*E_DIM);
  const float4* k1 = reinterpret_cast<const float4*>(g_K + (size_t)(2*gw+1)*E_DIM);
  const float4* v0 = reinterpret_cast<const float4*>(g_V + (size_t)(2*gw  )*E_DIM);
  const float4* v1 = reinterpret_cast<const float4*>(g_V + (size_t)(2*gw+1)*E_DIM);
  float4*       ws = reinterpret_cast<float4*>(g_WS + (size_t)gw*E_DIM);

  float4 qa = q[2*lane],  qb = q[2*lane+1];
  float4 k0a = k0[2*lane], k0b = k0[2*lane+1];
  float4 k1a = k1[2*lane], k1b = k1[2*lane+1];

  float s0 = qa.x*k0a.x + qa.y*k0a.y + qa.z*k0a.z + qa.w*k0a.w
           + qb.x*k0b.x + qb.y*k0b.y + qb.z*k0b.z + qb.w*k0b.w;
  float s1 = qa.x*k1a.x + qa.y*k1a.y + qa.z*k1a.z + qa.w*k1a.w
           + qb.x*k1b.x + qb.y*k1b.y + qb.z*k1b.z + qb.w*k1b.w;

#pragma unroll
  for (int off = 4; off > 0; off >>= 1){            // reduce within 8-lane head group
    s0 += __shfl_xor_sync(0xffffffffu, s0, off);
    s1 += __shfl_xor_sync(0xffffffffu, s1, off);
  }
  s0 *= 0.125f;  s1 *= 0.125f;                       // 1/sqrt(D), D=64
  float mx = fmaxf(s0, s1);
  float e0 = __expf(s0 - mx), e1 = __expf(s1 - mx);
  float inv = 1.0f / (e0 + e1);
  float w0 = e0 * inv, w1 = e1 * inv;

  float4 v0a = v0[2*lane], v0b = v0[2*lane+1];
  float4 v1a = v1[2*lane], v1b = v1[2*lane+1];
  float4 oa, ob;
  oa.x = w0*v0a.x + w1*v1a.x;  oa.y = w0*v0a.y + w1*v1a.y;
  oa.z = w0*v0a.z + w1*v1a.z;  oa.w = w0*v0a.w + w1*v1a.w;
  ob.x = w0*v0b.x + w1*v1b.x;  ob.y = w0*v0b.y + w1*v1b.y;
  ob.z = w0*v0b.z + w1*v1b.z;  ob.w = w0*v0b.w + w1*v1b.w;
  ws[2*lane]   = oa;
  ws[2*lane+1] = ob;
}

// ---------------- launch ----------------
extern "C" void kernel_launch(void* const* d_in, const int* in_sizes, int n_in,
                              void* d_out, int out_size)
{
  const float* p  = (const float*)d_in[0];  // (B,S,A,1,E)  -> [65536,256]
  const float* c  = (const float*)d_in[1];  // (B,S,A,2,E)  -> [131072,256]
  const float* Wq = (const float*)d_in[2];
  const float* bq = (const float*)d_in[3];
  const float* Wk = (const float*)d_in[4];
  const float* bk = (const float*)d_in[5];
  const float* Wv = (const float*)d_in[6];
  const float* bv = (const float*)d_in[7];
  const float* Wo = (const float*)d_in[8];
  const float* bo = (const float*)d_in[9];
  float* out = (float*)d_out;

  cudaFuncSetAttribute(gemm_split, cudaFuncAttributeMaxDynamicSharedMemorySize, SMEM_TOTAL);

  prep_weights<<<256, 256>>>(Wq, Wk, Wv, Wo);
  // Q = p @ Wq^T + bq
  gemm_split<<<dim3(2, MQ/128), 512, SMEM_TOTAL>>>(p, 0, 0,0, 0,0, bq, bq, nullptr);
  // K and V fused over one pass of c
  gemm_split<<<dim3(4, MC/128), 512, SMEM_TOTAL>>>(c, 0, 1,2, 1,2, bk, bv, nullptr);
  attn_kernel<<<MQ/8, 256>>>();
  // out = WS @ Wo^T + bo
  gemm_split<<<dim3(2, MQ/128), 512, SMEM_TOTAL>>>(nullptr, 1, 3,3, 3,3, bo, bo, out);
}

// round 4
// speedup vs baseline: 1.5462x; 1.3598x over previous
#include <cuda_runtime.h>
#include <cuda_fp16.h>
#include <cstdint>

#define E_DIM 256
#define MQ (64*8*128)     /* 65536 query tokens  */
#define MC (2*MQ)         /* 131072 constant rows */

// ---------------- scratch (allocation-free: __device__ globals) ----------------
__device__ float g_Q [(size_t)MQ*E_DIM];
__device__ float g_K [(size_t)MC*E_DIM];
__device__ float g_V [(size_t)MC*E_DIM];
__device__ float g_WS[(size_t)MQ*E_DIM];
__device__ __half g_Wf[4][E_DIM*E_DIM];

// Swizzled smem offset (fp16 elements). Tile is [128 rows][32 cols], row = 64B.
// 16B groups XOR-swizzled by ((row>>1)&3) -> conflict-free ldmatrix & STS.
__device__ __forceinline__ int sw_off(int row, int col){
  return row*32 + (((((col>>3) ^ ((row>>1)&3))) << 3) | (col & 7));
}

__device__ __forceinline__ void ldm4(uint32_t addr, uint32_t r[4]){
  asm volatile("ldmatrix.sync.aligned.m8n8.x4.shared.b16 {%0,%1,%2,%3}, [%4];\n"
    : "=r"(r[0]),"=r"(r[1]),"=r"(r[2]),"=r"(r[3]) : "r"(addr));
}

__device__ __forceinline__ void ldfrag(const __half* s, int rbase, int ks,
                                       int lane, uint32_t r[4]){
  int row = rbase + (lane & 7) + ((lane & 8) ? 8 : 0);
  int col = ks + ((lane & 16) ? 8 : 0);
  uint32_t a = (uint32_t)__cvta_generic_to_shared(s + sw_off(row, col));
  ldm4(a, r);
}

__device__ __forceinline__ void mma16816(float c[4], const uint32_t a[4],
                                         uint32_t b0, uint32_t b1){
  asm volatile("mma.sync.aligned.m16n8k16.row.col.f32.f16.f16.f32 "
    "{%0,%1,%2,%3}, {%4,%5,%6,%7}, {%8,%9}, {%0,%1,%2,%3};\n"
    : "+f"(c[0]),"+f"(c[1]),"+f"(c[2]),"+f"(c[3])
    : "r"(a[0]),"r"(a[1]),"r"(a[2]),"r"(a[3]), "r"(b0),"r"(b1));
}

__device__ __forceinline__ void cp_async16(uint32_t dst, const void* src){
  asm volatile("cp.async.cg.shared.global [%0], [%1], 16;" :: "r"(dst), "l"(src));
}

// ---------------- weight fp16 prep ----------------
__global__ void prep_weights(const float* __restrict__ Wq, const float* __restrict__ Wk,
                             const float* __restrict__ Wv, const float* __restrict__ Wo){
  int i = blockIdx.x * blockDim.x + threadIdx.x;   // 0 .. 65535
  const float* src[4] = {Wq, Wk, Wv, Wo};
#pragma unroll
  for (int w = 0; w < 4; w++){
    g_Wf[w][i] = __float2half_rn(src[w][i]);
  }
}

// ---------------- GEMM: Y[M,256] = X[M,256] @ W[256,256]^T + bias ----------------
// single-pass fp16 MMA, fp32 accumulate (norm rel-err ~2e-4, under 1e-3 thresh).
// CTA tile 128x128, BK=32, 16 warps (wm 0..3 x wn 0..3), warp tile 32x32.
// Double-buffered smem; cp.async for fp16 B; register-staged A convert.
// smem stage: A(8K) B(8K) = 16KB; two stages = 32KB dynamic.
#define STAGE_BYTES (2*2*128*32)
#define SMEM_TOTAL  (2*STAGE_BYTES)

__global__ void __launch_bounds__(512, 1)
gemm_f16(const float* __restrict__ Xext, int xsel,
         int wA, int wB, int yA, int yB,
         const float* __restrict__ biasA, const float* __restrict__ biasB,
         float* __restrict__ Yext)
{
  extern __shared__ __align__(128) char smem[];

  const int sel  = (int)(blockIdx.x >> 1);
  const int widx = sel ? wB : wA;
  const int ysel = sel ? yB : yA;
  const float* __restrict__ bias = sel ? biasB : biasA;
  const float* __restrict__ X = xsel ? g_WS : Xext;
  float* __restrict__ Y = (ysel==0)?g_Q : (ysel==1)?g_K : (ysel==2)?g_V : Yext;
  const __half* __restrict__ W = g_Wf[widx];

  const int tid  = threadIdx.x;
  const int lane = tid & 31;
  const int warp = tid >> 5;
  const int wm   = warp & 3;        // rows wm*32
  const int wn   = warp >> 2;       // cols wn*32
  const size_t mBase = (size_t)blockIdx.y * 128;
  const int    nBase = (int)(blockIdx.x & 1) * 128;

  __half* sA[2]; __half* sB[2];
#pragma unroll
  for (int s = 0; s < 2; s++){
    char* st = smem + s * STAGE_BYTES;
    sA[s] = reinterpret_cast<__half*>(st);
    sB[s] = reinterpret_cast<__half*>(st + 8192);
  }

  const float* __restrict__ Xbase = X + mBase * E_DIM;

  // A fill: 1024 float4 slots / 512 threads = 2 each. row = slot>>3 (8 f4/row)
  const int arow0 = tid >> 3,        ac4 = tid & 7;           // slot  t
  const int arow1 = (tid + 512) >> 3;                          // slot  t+512
  // B cp.async: 512 16B chunks: row = t>>2, chunk col = (t&3)*8
  const int brow = tid >> 2, bc8 = (tid & 3) * 8;
  const size_t bgo = (size_t)(nBase + brow) * E_DIM + bc8;

  float4 ra0, ra1;
  auto loadA = [&](int kk){
    ra0 = *reinterpret_cast<const float4*>(Xbase + (size_t)arow0*E_DIM + kk + ac4*4);
    ra1 = *reinterpret_cast<const float4*>(Xbase + (size_t)arow1*E_DIM + kk + ac4*4);
  };
  auto issueB = [&](int kk, int s){
    uint32_t db = (uint32_t)__cvta_generic_to_shared(&sB[s][sw_off(brow, bc8)]);
    cp_async16(db, W + bgo + kk);
    asm volatile("cp.async.commit_group;" ::: "memory");
  };
  auto storeA = [&](int s){
#pragma unroll
    for (int i = 0; i < 2; i++){
      float4 v = i ? ra1 : ra0;
      int row = i ? arow1 : arow0;
      __half2 h0 = __float22half2_rn(make_float2(v.x, v.y));
      __half2 h1 = __float22half2_rn(make_float2(v.z, v.w));
      int o0 = sw_off(row, ac4*4);
      *reinterpret_cast<__half2*>(&sA[s][o0])   = h0;
      *reinterpret_cast<__half2*>(&sA[s][o0+2]) = h1;
    }
  };

  float acc[2][4][4];
#pragma unroll
  for (int i=0;i<2;i++)
#pragma unroll
    for (int j=0;j<4;j++)
#pragma unroll
      for (int k=0;k<4;k++) acc[i][j][k] = 0.f;

  // prologue: fill stage 0
  issueB(0, 0);
  loadA(0);
  storeA(0);
  asm volatile("cp.async.wait_group 0;" ::: "memory");
  __syncthreads();

  for (int kc = 0; kc < 8; kc++){
    const int cur = kc & 1, nxt = cur ^ 1;
    if (kc < 7){
      issueB((kc+1)*32, nxt);     // async engine starts immediately
      loadA((kc+1)*32);           // global->reg, latency hidden by compute
    }

    // ---- compute on stage cur ----
#pragma unroll
    for (int ks2 = 0; ks2 < 2; ks2++){
      const int ks = ks2*16;
      uint32_t Af[2][4], Bf[2][4];
#pragma unroll
      for (int mt=0; mt<2; mt++)
        ldfrag(sA[cur], wm*32 + mt*16, ks, lane, Af[mt]);
#pragma unroll
      for (int bt=0; bt<2; bt++)
        ldfrag(sB[cur], wn*32 + bt*16, ks, lane, Bf[bt]);
#pragma unroll
      for (int mt=0; mt<2; mt++)
#pragma unroll
        for (int nt=0; nt<4; nt++){
          const int bt = nt >> 1, od = nt & 1;
          mma16816(acc[mt][nt], Af[mt], Bf[bt][od], Bf[bt][2+od]);
        }
    }

    if (kc < 7){
      storeA(nxt);                                  // convert + STS into next stage
      asm volatile("cp.async.wait_group 0;" ::: "memory");
    }
    __syncthreads();
  }

  // epilogue: +bias, fp32 stores
#pragma unroll
  for (int mt=0; mt<2; mt++){
#pragma unroll
    for (int nt=0; nt<4; nt++){
      size_t m = mBase + wm*32 + mt*16 + (lane>>2);
      int    n = nBase + wn*32 + nt*8 + (lane&3)*2;
      float b0 = bias[n], b1 = bias[n+1];
      float2 v0 = make_float2(acc[mt][nt][0] + b0, acc[mt][nt][1] + b1);
      float2 v1 = make_float2(acc[mt][nt][2] + b0, acc[mt][nt][3] + b1);
      *reinterpret_cast<float2*>(Y + m*E_DIM + n)      = v0;
      *reinterpret_cast<float2*>(Y + (m+8)*E_DIM + n)  = v1;
    }
  }
}

// ---------------- attention: warp per token, fp32, 2-key softmax ----------------
__global__ void __launch_bounds__(256)
attn_kernel()
{
  const int gw   = (blockIdx.x * 256 + threadIdx.x) >> 5;  // token id
  const int lane = threadIdx.x & 31;                        // 8 lanes per head

  const float4* q  = reinterpret_cast<const float4*>(g_Q + (size_t)gw*E_DIM);
  const float4* k0 = reinterpret_cast<const float4*>(g_K + (size_t)(2*gw  )*E_DIM);
  const float4* k1 = reinterpret_cast<const float4*>(g_K + (size_t)(2*gw+1)*E_DIM);
  const float4* v0 = reinterpret_cast<const float4*>(g_V + (size_t)(2*gw  )*E_DIM);
  const float4* v1 = reinterpret_cast<const float4*>(g_V + (size_t)(2*gw+1)*E_DIM);
  float4*       ws = reinterpret_cast<float4*>(g_WS + (size_t)gw*E_DIM);

  float4 qa = q[2*lane],  qb = q[2*lane+1];
  float4 k0a = k0[2*lane], k0b = k0[2*lane+1];
  float4 k1a = k1[2*lane], k1b = k1[2*lane+1];

  float s0 = qa.x*k0a.x + qa.y*k0a.y + qa.z*k0a.z + qa.w*k0a.w
           + qb.x*k0b.x + qb.y*k0b.y + qb.z*k0b.z + qb.w*k0b.w;
  float s1 = qa.x*k1a.x + qa.y*k1a.y + qa.z*k1a.z + qa.w*k1a.w
           + qb.x*k1b.x + qb.y*k1b.y + qb.z*k1b.z + qb.w*k1b.w;

#pragma unroll
  for (int off = 4; off > 0; off >>= 1){            // reduce within 8-lane head group
    s0 += __shfl_xor_sync(0xffffffffu, s0, off);
    s1 += __shfl_xor_sync(0xffffffffu, s1, off);
  }
  s0 *= 0.125f;  s1 *= 0.125f;                       // 1/sqrt(D), D=64
  float mx = fmaxf(s0, s1);
  float e0 = __expf(s0 - mx), e1 = __expf(s1 - mx);
  float inv = 1.0f / (e0 + e1);
  float w0 = e0 * inv, w1 = e1 * inv;

  float4 v0a = v0[2*lane], v0b = v0[2*lane+1];
  float4 v1a = v1[2*lane], v1b = v1[2*lane+1];
  float4 oa, ob;
  oa.x = w0*v0a.x + w1*v1a.x;  oa.y = w0*v0a.y + w1*v1a.y;
  oa.z = w0*v0a.z + w1*v1a.z;  oa.w = w0*v0a.w + w1*v1a.w;
  ob.x = w0*v0b.x + w1*v1b.x;  ob.y = w0*v0b.y + w1*v1b.y;
  ob.z = w0*v0b.z + w1*v1b.z;  ob.w = w0*v0b.w + w1*v1b.w;
  ws[2*lane]   = oa;
  ws[2*lane+1] = ob;
}

// ---------------- launch ----------------
extern "C" void kernel_launch(void* const* d_in, const int* in_sizes, int n_in,
                              void* d_out, int out_size)
{
  const float* p  = (const float*)d_in[0];  // (B,S,A,1,E)  -> [65536,256]
  const float* c  = (const float*)d_in[1];  // (B,S,A,2,E)  -> [131072,256]
  const float* Wq = (const float*)d_in[2];
  const float* bq = (const float*)d_in[3];
  const float* Wk = (const float*)d_in[4];
  const float* bk = (const float*)d_in[5];
  const float* Wv = (const float*)d_in[6];
  const float* bv = (const float*)d_in[7];
  const float* Wo = (const float*)d_in[8];
  const float* bo = (const float*)d_in[9];
  float* out = (float*)d_out;

  cudaFuncSetAttribute(gemm_f16, cudaFuncAttributeMaxDynamicSharedMemorySize, SMEM_TOTAL);

  prep_weights<<<256, 256>>>(Wq, Wk, Wv, Wo);
  // Q = p @ Wq^T + bq
  gemm_f16<<<dim3(2, MQ/128), 512, SMEM_TOTAL>>>(p, 0, 0,0, 0,0, bq, bq, nullptr);
  // K and V fused over one pass of c
  gemm_f16<<<dim3(4, MC/128), 512, SMEM_TOTAL>>>(c, 0, 1,2, 1,2, bk, bv, nullptr);
  attn_kernel<<<MQ/8, 256>>>();
  // out = WS @ Wo^T + bo
  gemm_f16<<<dim3(2, MQ/128), 512, SMEM_TOTAL>>>(nullptr, 1, 3,3, 3,3, bo, bo, out);
}

// round 5
// speedup vs baseline: 1.8175x; 1.1755x over previous
#include <cuda_runtime.h>
#include <cuda_fp16.h>
#include <cstdint>

#define E_DIM 256
#define MQ (64*8*128)     /* 65536 query tokens  */
#define MC (2*MQ)         /* 131072 constant rows */

// ---------------- scratch (allocation-free: __device__ globals) ----------------
__device__ __half g_Qh [(size_t)MQ*E_DIM];
__device__ __half g_Kh [(size_t)MC*E_DIM];
__device__ __half g_Vh [(size_t)MC*E_DIM];
__device__ __half g_WSh[(size_t)MQ*E_DIM];
__device__ __half g_Wf[4][E_DIM*E_DIM];

// Swizzled smem offset (fp16 elements). Row = 32 cols = 64B.
// 16B groups XOR-swizzled by ((row>>1)&3) -> conflict-free ldmatrix & STS.
__device__ __forceinline__ int sw_off(int row, int col){
  return row*32 + (((((col>>3) ^ ((row>>1)&3))) << 3) | (col & 7));
}

__device__ __forceinline__ void ldm4(uint32_t addr, uint32_t r[4]){
  asm volatile("ldmatrix.sync.aligned.m8n8.x4.shared.b16 {%0,%1,%2,%3}, [%4];\n"
    : "=r"(r[0]),"=r"(r[1]),"=r"(r[2]),"=r"(r[3]) : "r"(addr));
}

__device__ __forceinline__ void ldfrag(const __half* s, int rbase, int ks,
                                       int lane, uint32_t r[4]){
  int row = rbase + (lane & 7) + ((lane & 8) ? 8 : 0);
  int col = ks + ((lane & 16) ? 8 : 0);
  uint32_t a = (uint32_t)__cvta_generic_to_shared(s + sw_off(row, col));
  ldm4(a, r);
}

__device__ __forceinline__ void mma16816(float c[4], const uint32_t a[4],
                                         uint32_t b0, uint32_t b1){
  asm volatile("mma.sync.aligned.m16n8k16.row.col.f32.f16.f16.f32 "
    "{%0,%1,%2,%3}, {%4,%5,%6,%7}, {%8,%9}, {%0,%1,%2,%3};\n"
    : "+f"(c[0]),"+f"(c[1]),"+f"(c[2]),"+f"(c[3])
    : "r"(a[0]),"r"(a[1]),"r"(a[2]),"r"(a[3]), "r"(b0),"r"(b1));
}

__device__ __forceinline__ void cp_async16(uint32_t dst, const void* src){
  asm volatile("cp.async.cg.shared.global [%0], [%1], 16;" :: "r"(dst), "l"(src));
}

// ---------------- weight fp16 prep ----------------
__global__ void prep_weights(const float* __restrict__ Wq, const float* __restrict__ Wk,
                             const float* __restrict__ Wv, const float* __restrict__ Wo){
  int i = blockIdx.x * blockDim.x + threadIdx.x;   // 0 .. 65535
  const float* src[4] = {Wq, Wk, Wv, Wo};
#pragma unroll
  for (int w = 0; w < 4; w++){
    g_Wf[w][i] = __float2half_rn(src[w][i]);
  }
}

// ---------------- GEMM: Y[M,256] = X[M,256] @ W[256,256]^T + bias ----------------
// fp16 MMA, fp32 accumulate. CTA tile 128x256 (A read ONCE), BK=32,
// 16 warps 32x32 x 2 N-halves. Double buffer; cp.async for B (and A when fp16).
// stage: A 128x32 (8K) + B 256x32 (16K) = 24KB; x2 = 48KB dynamic.
#define STAGE_BYTES 24576
#define SMEM_TOTAL  (2*STAGE_BYTES)

__global__ void __launch_bounds__(512, 1)
gemm_f16(const float* __restrict__ Xext, int aHalf,
         int wA, int wB, int yA, int yB,
         const float* __restrict__ biasA, const float* __restrict__ biasB,
         float* __restrict__ Yext)
{
  extern __shared__ __align__(128) char smem[];

  const int sel  = (int)blockIdx.x;         // 0 or 1 (fused KV); 0 otherwise
  const int widx = sel ? wB : wA;
  const int ysel = sel ? yB : yA;
  const float* __restrict__ bias = sel ? biasB : biasA;
  const __half* __restrict__ Xh = g_WSh;    // fp16 A source (O GEMM)
  const float*  __restrict__ Xf = Xext;     // fp32 A source (proj GEMMs)
  __half* __restrict__ Yh = (ysel==0)?g_Qh : (ysel==1)?g_Kh : g_Vh;
  const __half* __restrict__ W = g_Wf[widx];

  const int tid  = threadIdx.x;
  const int lane = tid & 31;
  const int warp = tid >> 5;
  const int wm   = warp & 3;        // rows wm*32
  const int wn   = warp >> 2;       // cols wn*32 (within each 128 half)
  const size_t mBase = (size_t)blockIdx.y * 128;

  __half* sA[2]; __half* sB[2];
#pragma unroll
  for (int s = 0; s < 2; s++){
    char* st = smem + s * STAGE_BYTES;
    sA[s] = reinterpret_cast<__half*>(st);
    sB[s] = reinterpret_cast<__half*>(st + 8192);
  }

  // ---- A fill indices ----
  // fp32 path: 1024 float4 slots (128 rows x 8 f4), 2 per thread
  const int arow0 = tid >> 3,       ac4 = tid & 7;
  const int arow1 = (tid + 512) >> 3;
  // fp16 path: 512 16B chunks (128 rows x 4), 1 per thread
  const int harow = tid >> 2,       hac8 = (tid & 3) * 8;
  // ---- B fill: 1024 16B chunks (256 rows x 4), 2 per thread ----
  const int brow = tid >> 2, bc8 = (tid & 3) * 8;

  float4 ra0, ra1;
  auto loadA = [&](int kk){
    const float* xb = Xf + mBase * E_DIM + kk;
    ra0 = *reinterpret_cast<const float4*>(xb + (size_t)arow0*E_DIM + ac4*4);
    ra1 = *reinterpret_cast<const float4*>(xb + (size_t)arow1*E_DIM + ac4*4);
  };
  auto storeA = [&](int s){
#pragma unroll
    for (int i = 0; i < 2; i++){
      float4 v = i ? ra1 : ra0;
      int row = i ? arow1 : arow0;
      __half2 h0 = __float22half2_rn(make_float2(v.x, v.y));
      __half2 h1 = __float22half2_rn(make_float2(v.z, v.w));
      int o0 = sw_off(row, ac4*4);
      *reinterpret_cast<__half2*>(&sA[s][o0])   = h0;
      *reinterpret_cast<__half2*>(&sA[s][o0+2]) = h1;
    }
  };
  auto issueAsync = [&](int kk, int s){
    if (aHalf){
      uint32_t da = (uint32_t)__cvta_generic_to_shared(&sA[s][sw_off(harow, hac8)]);
      cp_async16(da, Xh + (mBase + harow)*E_DIM + kk + hac8);
    }
    uint32_t db0 = (uint32_t)__cvta_generic_to_shared(&sB[s][sw_off(brow, bc8)]);
    uint32_t db1 = (uint32_t)__cvta_generic_to_shared(&sB[s][sw_off(brow+128, bc8)]);
    cp_async16(db0, W + (size_t)brow*E_DIM + kk + bc8);
    cp_async16(db1, W + (size_t)(brow+128)*E_DIM + kk + bc8);
    asm volatile("cp.async.commit_group;" ::: "memory");
  };

  float acc[2][2][4][4];   // [nhalf][mt][nt][4]
#pragma unroll
  for (int h=0;h<2;h++)
#pragma unroll
    for (int i=0;i<2;i++)
#pragma unroll
      for (int j=0;j<4;j++)
#pragma unroll
        for (int k=0;k<4;k++) acc[h][i][j][k] = 0.f;

  // prologue: fill stage 0
  issueAsync(0, 0);
  if (!aHalf){ loadA(0); storeA(0); }
  asm volatile("cp.async.wait_group 0;" ::: "memory");
  __syncthreads();

  for (int kc = 0; kc < 8; kc++){
    const int cur = kc & 1, nxt = cur ^ 1;
    if (kc < 7){
      issueAsync((kc+1)*32, nxt);
      if (!aHalf) loadA((kc+1)*32);
    }

    // ---- compute on stage cur ----
#pragma unroll
    for (int ks2 = 0; ks2 < 2; ks2++){
      const int ks = ks2*16;
      uint32_t Af[2][4], Bf[2][2][4];
#pragma unroll
      for (int mt=0; mt<2; mt++)
        ldfrag(sA[cur], wm*32 + mt*16, ks, lane, Af[mt]);
#pragma unroll
      for (int nh=0; nh<2; nh++)
#pragma unroll
        for (int bt=0; bt<2; bt++)
          ldfrag(sB[cur], nh*128 + wn*32 + bt*16, ks, lane, Bf[nh][bt]);
#pragma unroll
      for (int nh=0; nh<2; nh++)
#pragma unroll
        for (int mt=0; mt<2; mt++)
#pragma unroll
          for (int nt=0; nt<4; nt++){
            const int bt = nt >> 1, od = nt & 1;
            mma16816(acc[nh][mt][nt], Af[mt], Bf[nh][bt][od], Bf[nh][bt][2+od]);
          }
    }

    if (kc < 7){
      if (!aHalf) storeA(nxt);
      asm volatile("cp.async.wait_group 0;" ::: "memory");
    }
    __syncthreads();
  }

  // epilogue: +bias; fp16 stores (Q/K/V/WS) or fp32 (final out)
#pragma unroll
  for (int nh=0; nh<2; nh++){
#pragma unroll
    for (int mt=0; mt<2; mt++){
#pragma unroll
      for (int nt=0; nt<4; nt++){
        size_t m = mBase + wm*32 + mt*16 + (lane>>2);
        int    n = nh*128 + wn*32 + nt*8 + (lane&3)*2;
        float b0 = bias[n], b1 = bias[n+1];
        float* a = acc[nh][mt][nt];
        if (ysel == 3){
          *reinterpret_cast<float2*>(Yext + m*E_DIM + n)     = make_float2(a[0]+b0, a[1]+b1);
          *reinterpret_cast<float2*>(Yext + (m+8)*E_DIM + n) = make_float2(a[2]+b0, a[3]+b1);
        } else {
          *reinterpret_cast<__half2*>(Yh + m*E_DIM + n)     = __floats2half2_rn(a[0]+b0, a[1]+b1);
          *reinterpret_cast<__half2*>(Yh + (m+8)*E_DIM + n) = __floats2half2_rn(a[2]+b0, a[3]+b1);
        }
      }
    }
  }
}

// ---------------- attention: warp per token, fp32 math on fp16 data ------------
__device__ __forceinline__ float dot8(uint4 a, uint4 b){
  const __half2* ah = reinterpret_cast<const __half2*>(&a);
  const __half2* bh = reinterpret_cast<const __half2*>(&b);
  float s = 0.f;
#pragma unroll
  for (int i = 0; i < 4; i++){
    float2 af = __half22float2(ah[i]);
    float2 bf = __half22float2(bh[i]);
    s += af.x*bf.x + af.y*bf.y;
  }
  return s;
}

__global__ void __launch_bounds__(256)
attn_kernel()
{
  const int gw   = (blockIdx.x * 256 + threadIdx.x) >> 5;  // token id
  const int lane = threadIdx.x & 31;                        // 8 lanes per head

  const uint4* q  = reinterpret_cast<const uint4*>(g_Qh + (size_t)gw*E_DIM);
  const uint4* k0 = reinterpret_cast<const uint4*>(g_Kh + (size_t)(2*gw  )*E_DIM);
  const uint4* k1 = reinterpret_cast<const uint4*>(g_Kh + (size_t)(2*gw+1)*E_DIM);
  const uint4* v0 = reinterpret_cast<const uint4*>(g_Vh + (size_t)(2*gw  )*E_DIM);
  const uint4* v1 = reinterpret_cast<const uint4*>(g_Vh + (size_t)(2*gw+1)*E_DIM);
  uint4*       ws = reinterpret_cast<uint4*>(g_WSh + (size_t)gw*E_DIM);

  uint4 qa = q[lane];
  float s0 = dot8(qa, k0[lane]);
  float s1 = dot8(qa, k1[lane]);

#pragma unroll
  for (int off = 4; off > 0; off >>= 1){            // reduce within 8-lane head group
    s0 += __shfl_xor_sync(0xffffffffu, s0, off);
    s1 += __shfl_xor_sync(0xffffffffu, s1, off);
  }
  s0 *= 0.125f;  s1 *= 0.125f;                       // 1/sqrt(D), D=64
  float mx = fmaxf(s0, s1);
  float e0 = __expf(s0 - mx), e1 = __expf(s1 - mx);
  float inv = 1.0f / (e0 + e1);
  float w0 = e0 * inv, w1 = e1 * inv;

  uint4 va = v0[lane], vb = v1[lane];
  const __half2* vah = reinterpret_cast<const __half2*>(&va);
  const __half2* vbh = reinterpret_cast<const __half2*>(&vb);
  uint4 o;
  __half2* oh = reinterpret_cast<__half2*>(&o);
#pragma unroll
  for (int i = 0; i < 4; i++){
    float2 a = __half22float2(vah[i]);
    float2 b = __half22float2(vbh[i]);
    oh[i] = __floats2half2_rn(w0*a.x + w1*b.x, w0*a.y + w1*b.y);
  }
  ws[lane] = o;
}

// ---------------- launch ----------------
extern "C" void kernel_launch(void* const* d_in, const int* in_sizes, int n_in,
                              void* d_out, int out_size)
{
  const float* p  = (const float*)d_in[0];  // (B,S,A,1,E)  -> [65536,256]
  const float* c  = (const float*)d_in[1];  // (B,S,A,2,E)  -> [131072,256]
  const float* Wq = (const float*)d_in[2];
  const float* bq = (const float*)d_in[3];
  const float* Wk = (const float*)d_in[4];
  const float* bk = (const float*)d_in[5];
  const float* Wv = (const float*)d_in[6];
  const float* bv = (const float*)d_in[7];
  const float* Wo = (const float*)d_in[8];
  const float* bo = (const float*)d_in[9];
  float* out = (float*)d_out;

  cudaFuncSetAttribute(gemm_f16, cudaFuncAttributeMaxDynamicSharedMemorySize, SMEM_TOTAL);

  prep_weights<<<256, 256>>>(Wq, Wk, Wv, Wo);
  // Q = p @ Wq^T + bq
  gemm_f16<<<dim3(1, MQ/128), 512, SMEM_TOTAL>>>(p, 0, 0,0, 0,0, bq, bq, nullptr);
  // K and V fused over one pass of c
  gemm_f16<<<dim3(2, MC/128), 512, SMEM_TOTAL>>>(c, 0, 1,2, 1,2, bk, bv, nullptr);
  attn_kernel<<<MQ/8, 256>>>();
  // out = WS @ Wo^T + bo  (A already fp16 -> cp.async path)
  gemm_f16<<<dim3(1, MQ/128), 512, SMEM_TOTAL>>>(nullptr, 1, 3,3, 3,3, bo, bo, out);
}

// round 6
// speedup vs baseline: 1.8804x; 1.0346x over previous
#include <cuda_runtime.h>
#include <cuda_fp16.h>
#include <cstdint>

#define E_DIM 256
#define MQ (64*8*128)     /* 65536 query tokens  */
#define MC (2*MQ)         /* 131072 constant rows */

// ---------------- scratch (allocation-free: __device__ globals) ----------------
__device__ __half g_Qh [(size_t)MQ*E_DIM];
__device__ __half g_Kh [(size_t)MC*E_DIM];
__device__ __half g_Vh [(size_t)MC*E_DIM];
__device__ __half g_WSh[(size_t)MQ*E_DIM];
__device__ __half g_Wf[4][E_DIM*E_DIM];

// Swizzled smem offset (fp16 elements). Row = 32 cols = 64B.
__device__ __forceinline__ int sw_off(int row, int col){
  return row*32 + (((((col>>3) ^ ((row>>1)&3))) << 3) | (col & 7));
}

__device__ __forceinline__ void ldm4(uint32_t addr, uint32_t r[4]){
  asm volatile("ldmatrix.sync.aligned.m8n8.x4.shared.b16 {%0,%1,%2,%3}, [%4];\n"
    : "=r"(r[0]),"=r"(r[1]),"=r"(r[2]),"=r"(r[3]) : "r"(addr));
}

__device__ __forceinline__ void mma16816(float c[4], const uint32_t a[4],
                                         uint32_t b0, uint32_t b1){
  asm volatile("mma.sync.aligned.m16n8k16.row.col.f32.f16.f16.f32 "
    "{%0,%1,%2,%3}, {%4,%5,%6,%7}, {%8,%9}, {%0,%1,%2,%3};\n"
    : "+f"(c[0]),"+f"(c[1]),"+f"(c[2]),"+f"(c[3])
    : "r"(a[0]),"r"(a[1]),"r"(a[2]),"r"(a[3]), "r"(b0),"r"(b1));
}

__device__ __forceinline__ void cp_async16(uint32_t dst, const void* src){
  asm volatile("cp.async.cg.shared.global [%0], [%1], 16;" :: "r"(dst), "l"(src));
}
#define CP_COMMIT() asm volatile("cp.async.commit_group;" ::: "memory")
#define CP_WAIT1()  asm volatile("cp.async.wait_group 1;" ::: "memory")
#define CP_WAIT0()  asm volatile("cp.async.wait_group 0;" ::: "memory")

// ---------------- weight fp16 prep ----------------
__global__ void prep_weights(const float* __restrict__ Wq, const float* __restrict__ Wk,
                             const float* __restrict__ Wv, const float* __restrict__ Wo){
  int i = blockIdx.x * blockDim.x + threadIdx.x;   // 0 .. 65535
  const float* src[4] = {Wq, Wk, Wv, Wo};
#pragma unroll
  for (int w = 0; w < 4; w++){
    g_Wf[w][i] = __float2half_rn(src[w][i]);
  }
}

// ---------------- GEMM: Y[128tile,256] = X @ W^T + bias -------------------------
// fp16 MMA, fp32 acc. CTA tile 128x256, BK=32, 3-stage cp.async pipeline.
// phase 0: merged Q/K/V job table (fp32 A, convert in-register; fp16 stores)
// phase 1: O GEMM (fp16 A via cp.async; fp32 stores)
// stage: A 128x32 (8K) + B 256x32 (16K) = 24KB; x3 = 72KB dynamic.
#define STAGE_BYTES 24576
#define SMEM_TOTAL  (3*STAGE_BYTES)

__global__ void __launch_bounds__(512, 1)
gemm_all(const float* __restrict__ p, const float* __restrict__ c,
         const float* __restrict__ bq, const float* __restrict__ bk,
         const float* __restrict__ bv, const float* __restrict__ bo,
         float* __restrict__ out, int phase)
{
  extern __shared__ __align__(128) char smem[];

  const int job = (int)blockIdx.x;
  const float* __restrict__ Xf = nullptr;
  const __half* __restrict__ Wm;
  __half* __restrict__ Yh = nullptr;
  const float* __restrict__ bias;
  size_t mBase;
  if (phase == 1){
    Wm = g_Wf[3]; bias = bo; mBase = (size_t)job * 128;
  } else if (job < 512){
    Xf = p;  Wm = g_Wf[0]; Yh = g_Qh; bias = bq; mBase = (size_t)job * 128;
  } else {
    const int pair = (job - 512) >> 1, kv = (job - 512) & 1;
    Xf = c;  mBase = (size_t)pair * 128;
    if (kv == 0){ Wm = g_Wf[1]; Yh = g_Kh; bias = bk; }
    else        { Wm = g_Wf[2]; Yh = g_Vh; bias = bv; }
  }

  const int tid  = threadIdx.x;
  const int lane = tid & 31;
  const int warp = tid >> 5;
  const int wm   = warp & 3;        // rows wm*32
  const int wn   = warp >> 2;       // cols wn*32 (within each 128 half)

  __half* sA[3]; __half* sB[3];
#pragma unroll
  for (int s = 0; s < 3; s++){
    char* st = smem + s * STAGE_BYTES;
    sA[s] = reinterpret_cast<__half*>(st);
    sB[s] = reinterpret_cast<__half*>(st + 8192);
  }

  // ---- fill indices ----
  const int arow0 = tid >> 3,  ac4 = tid & 7;       // fp32 A: 2 float4 per thread
  const int arow1 = (tid + 512) >> 3;
  const int harow = tid >> 2,  hac8 = (tid & 3)*8;  // fp16 A: 1x16B per thread
  const int brow  = tid >> 2,  bc8  = (tid & 3)*8;  // B: 2x16B per thread

  float4 ra0, ra1;
  auto loadA = [&](int kk){
    const float* xb = Xf + mBase * E_DIM + kk;
    ra0 = *reinterpret_cast<const float4*>(xb + (size_t)arow0*E_DIM + ac4*4);
    ra1 = *reinterpret_cast<const float4*>(xb + (size_t)arow1*E_DIM + ac4*4);
  };
  auto storeA = [&](int s){
#pragma unroll
    for (int i = 0; i < 2; i++){
      float4 v = i ? ra1 : ra0;
      int row = i ? arow1 : arow0;
      __half2 h0 = __float22half2_rn(make_float2(v.x, v.y));
      __half2 h1 = __float22half2_rn(make_float2(v.z, v.w));
      int o0 = sw_off(row, ac4*4);
      *reinterpret_cast<__half2*>(&sA[s][o0])   = h0;
      *reinterpret_cast<__half2*>(&sA[s][o0+2]) = h1;
    }
  };
  auto issueAsync = [&](int kk, int s){
    if (phase == 1){
      uint32_t da = (uint32_t)__cvta_generic_to_shared(&sA[s][sw_off(harow, hac8)]);
      cp_async16(da, g_WSh + (mBase + harow)*E_DIM + kk + hac8);
    }
    uint32_t db0 = (uint32_t)__cvta_generic_to_shared(&sB[s][sw_off(brow, bc8)]);
    uint32_t db1 = (uint32_t)__cvta_generic_to_shared(&sB[s][sw_off(brow+128, bc8)]);
    cp_async16(db0, Wm + (size_t)brow*E_DIM + kk + bc8);
    cp_async16(db1, Wm + (size_t)(brow+128)*E_DIM + kk + bc8);
    CP_COMMIT();
  };

  float acc[2][2][4][4];   // [nhalf][mt][nt][4]
#pragma unroll
  for (int h=0;h<2;h++)
#pragma unroll
    for (int i=0;i<2;i++)
#pragma unroll
      for (int j=0;j<4;j++)
#pragma unroll
        for (int k=0;k<4;k++) acc[h][i][j][k] = 0.f;

  // prologue: stages 0 and 1 in flight
  issueAsync(0, 0);
  if (phase == 0){ loadA(0); storeA(0); }
  issueAsync(32, 1);
  if (phase == 0){ loadA(32); storeA(1); }

  for (int kc = 0; kc < 8; kc++){
    const int cur = kc % 3;
    if (kc < 6) CP_WAIT1(); else CP_WAIT0();
    __syncthreads();

    const int pre = kc + 2;
    if (pre < 8){
      const int ps = pre % 3;
      issueAsync(pre*32, ps);               // stage ps freed by this barrier
      if (phase == 0) loadA(pre*32);        // LDG latency hidden by compute below
    }

    // ---- compute on stage cur ----
#pragma unroll
    for (int ks2 = 0; ks2 < 2; ks2++){
      const int ks = ks2*16;
      uint32_t Af[2][4], Bf[2][2][4];
#pragma unroll
      for (int mt=0; mt<2; mt++){
        int row = wm*32 + mt*16 + (lane & 7) + ((lane & 8) ? 8 : 0);
        int col = ks + ((lane & 16) ? 8 : 0);
        ldm4((uint32_t)__cvta_generic_to_shared(sA[cur] + sw_off(row, col)), Af[mt]);
      }
#pragma unroll
      for (int nh=0; nh<2; nh++)
#pragma unroll
        for (int bt=0; bt<2; bt++){
          int row = nh*128 + wn*32 + bt*16 + (lane & 7) + ((lane & 8) ? 8 : 0);
          int col = ks + ((lane & 16) ? 8 : 0);
          ldm4((uint32_t)__cvta_generic_to_shared(sB[cur] + sw_off(row, col)), Bf[nh][bt]);
        }
#pragma unroll
      for (int nh=0; nh<2; nh++)
#pragma unroll
        for (int mt=0; mt<2; mt++)
#pragma unroll
          for (int nt=0; nt<4; nt++){
            const int bt = nt >> 1, od = nt & 1;
            mma16816(acc[nh][mt][nt], Af[mt], Bf[nh][bt][od], Bf[nh][bt][2+od]);
          }
    }

    if (pre < 8 && phase == 0) storeA(pre % 3);   // into stage freed this iter
  }

  // epilogue: +bias; fp16 stores (Q/K/V) or fp32 (final out)
#pragma unroll
  for (int nh=0; nh<2; nh++){
#pragma unroll
    for (int mt=0; mt<2; mt++){
#pragma unroll
      for (int nt=0; nt<4; nt++){
        size_t m = mBase + wm*32 + mt*16 + (lane>>2);
        int    n = nh*128 + wn*32 + nt*8 + (lane&3)*2;
        float b0 = bias[n], b1 = bias[n+1];
        float* a = acc[nh][mt][nt];
        if (phase == 1){
          *reinterpret_cast<float2*>(out + m*E_DIM + n)     = make_float2(a[0]+b0, a[1]+b1);
          *reinterpret_cast<float2*>(out + (m+8)*E_DIM + n) = make_float2(a[2]+b0, a[3]+b1);
        } else {
          *reinterpret_cast<__half2*>(Yh + m*E_DIM + n)     = __floats2half2_rn(a[0]+b0, a[1]+b1);
          *reinterpret_cast<__half2*>(Yh + (m+8)*E_DIM + n) = __floats2half2_rn(a[2]+b0, a[3]+b1);
        }
      }
    }
  }
}

// ---------------- attention: warp per token, fp32 math on fp16 data ------------
__device__ __forceinline__ float dot8(uint4 a, uint4 b){
  const __half2* ah = reinterpret_cast<const __half2*>(&a);
  const __half2* bh = reinterpret_cast<const __half2*>(&b);
  float s = 0.f;
#pragma unroll
  for (int i = 0; i < 4; i++){
    float2 af = __half22float2(ah[i]);
    float2 bf = __half22float2(bh[i]);
    s += af.x*bf.x + af.y*bf.y;
  }
  return s;
}

__global__ void __launch_bounds__(256)
attn_kernel()
{
  const int gw   = (blockIdx.x * 256 + threadIdx.x) >> 5;  // token id
  const int lane = threadIdx.x & 31;                        // 8 lanes per head

  const uint4* q  = reinterpret_cast<const uint4*>(g_Qh + (size_t)gw*E_DIM);
  const uint4* k0 = reinterpret_cast<const uint4*>(g_Kh + (size_t)(2*gw  )*E_DIM);
  const uint4* k1 = reinterpret_cast<const uint4*>(g_Kh + (size_t)(2*gw+1)*E_DIM);
  const uint4* v0 = reinterpret_cast<const uint4*>(g_Vh + (size_t)(2*gw  )*E_DIM);
  const uint4* v1 = reinterpret_cast<const uint4*>(g_Vh + (size_t)(2*gw+1)*E_DIM);
  uint4*       ws = reinterpret_cast<uint4*>(g_WSh + (size_t)gw*E_DIM);

  uint4 qa = q[lane];
  float s0 = dot8(qa, k0[lane]);
  float s1 = dot8(qa, k1[lane]);

#pragma unroll
  for (int off = 4; off > 0; off >>= 1){            // reduce within 8-lane head group
    s0 += __shfl_xor_sync(0xffffffffu, s0, off);
    s1 += __shfl_xor_sync(0xffffffffu, s1, off);
  }
  s0 *= 0.125f;  s1 *= 0.125f;                       // 1/sqrt(D), D=64
  float mx = fmaxf(s0, s1);
  float e0 = __expf(s0 - mx), e1 = __expf(s1 - mx);
  float inv = 1.0f / (e0 + e1);
  float w0 = e0 * inv, w1 = e1 * inv;

  uint4 va = v0[lane], vb = v1[lane];
  const __half2* vah = reinterpret_cast<const __half2*>(&va);
  const __half2* vbh = reinterpret_cast<const __half2*>(&vb);
  uint4 o;
  __half2* oh = reinterpret_cast<__half2*>(&o);
#pragma unroll
  for (int i = 0; i < 4; i++){
    float2 a = __half22float2(vah[i]);
    float2 b = __half22float2(vbh[i]);
    oh[i] = __floats2half2_rn(w0*a.x + w1*b.x, w0*a.y + w1*b.y);
  }
  ws[lane] = o;
}

// ---------------- launch ----------------
extern "C" void kernel_launch(void* const* d_in, const int* in_sizes, int n_in,
                              void* d_out, int out_size)
{
  const float* p  = (const float*)d_in[0];  // (B,S,A,1,E)  -> [65536,256]
  const float* c  = (const float*)d_in[1];  // (B,S,A,2,E)  -> [131072,256]
  const float* Wq = (const float*)d_in[2];
  const float* bq = (const float*)d_in[3];
  const float* Wk = (const float*)d_in[4];
  const float* bk = (const float*)d_in[5];
  const float* Wv = (const float*)d_in[6];
  const float* bv = (const float*)d_in[7];
  const float* Wo = (const float*)d_in[8];
  const float* bo = (const float*)d_in[9];
  float* out = (float*)d_out;

  cudaFuncSetAttribute(gemm_all, cudaFuncAttributeMaxDynamicSharedMemorySize, SMEM_TOTAL);

  prep_weights<<<256, 256>>>(Wq, Wk, Wv, Wo);
  // merged Q/K/V: 512 Q-tiles + 1024 (K,V) interleaved pairs
  gemm_all<<<2560, 512, SMEM_TOTAL>>>(p, c, bq, bk, bv, bo, out, 0);
  attn_kernel<<<MQ/8, 256>>>();
  // out = WS @ Wo^T + bo
  gemm_all<<<512, 512, SMEM_TOTAL>>>(p, c, bq, bk, bv, bo, out, 1);
}

// round 7
// speedup vs baseline: 1.9249x; 1.0236x over previous
#include <cuda_runtime.h>
#include <cuda_fp16.h>
#include <cstdint>

#define E_DIM 256
#define MQ (64*8*128)     /* 65536 query tokens  */
#define MC (2*MQ)         /* 131072 constant rows */

// ---------------- scratch (allocation-free: __device__ globals) ----------------
__device__ __half g_Qh [(size_t)MQ*E_DIM];
__device__ __half g_Kh [(size_t)MC*E_DIM];
__device__ __half g_Vh [(size_t)MC*E_DIM];
__device__ __half g_WSh[(size_t)MQ*E_DIM];
__device__ __half g_Wf[4][E_DIM*E_DIM];

// Swizzled smem offset (fp16 elements). Row = 32 cols = 64B.
__device__ __forceinline__ int sw_off(int row, int col){
  return row*32 + (((((col>>3) ^ ((row>>1)&3))) << 3) | (col & 7));
}

__device__ __forceinline__ void ldm4(uint32_t addr, uint32_t r[4]){
  asm volatile("ldmatrix.sync.aligned.m8n8.x4.shared.b16 {%0,%1,%2,%3}, [%4];\n"
    : "=r"(r[0]),"=r"(r[1]),"=r"(r[2]),"=r"(r[3]) : "r"(addr));
}

__device__ __forceinline__ void mma16816(float c[4], const uint32_t a[4],
                                         uint32_t b0, uint32_t b1){
  asm volatile("mma.sync.aligned.m16n8k16.row.col.f32.f16.f16.f32 "
    "{%0,%1,%2,%3}, {%4,%5,%6,%7}, {%8,%9}, {%0,%1,%2,%3};\n"
    : "+f"(c[0]),"+f"(c[1]),"+f"(c[2]),"+f"(c[3])
    : "r"(a[0]),"r"(a[1]),"r"(a[2]),"r"(a[3]), "r"(b0),"r"(b1));
}

__device__ __forceinline__ void cp_async16(uint32_t dst, const void* src){
  asm volatile("cp.async.cg.shared.global [%0], [%1], 16;" :: "r"(dst), "l"(src));
}
#define CP_COMMIT() asm volatile("cp.async.commit_group;" ::: "memory")
#define CP_WAIT2()  asm volatile("cp.async.wait_group 2;" ::: "memory")
#define CP_WAIT1()  asm volatile("cp.async.wait_group 1;" ::: "memory")
#define CP_WAIT0()  asm volatile("cp.async.wait_group 0;" ::: "memory")

// ---------------- weight fp16 prep ----------------
__global__ void prep_weights(const float* __restrict__ Wq, const float* __restrict__ Wk,
                             const float* __restrict__ Wv, const float* __restrict__ Wo){
  int i = blockIdx.x * blockDim.x + threadIdx.x;   // 0 .. 65535
  const float* src[4] = {Wq, Wk, Wv, Wo};
#pragma unroll
  for (int w = 0; w < 4; w++){
    g_Wf[w][i] = __float2half_rn(src[w][i]);
  }
}

// ---------------- GEMM: Y[128tile,128half] = X @ W^T + bias ---------------------
// fp16 MMA, fp32 acc. CTA tile 128x128, 256 threads, 2 CTAs/SM, BK=32,
// 4-stage cp.async pipeline (wait_group 2).
// phase 0: merged Q/K/V job table (fp32 A, in-register convert; fp16 stores)
// phase 1: O GEMM (fp16 A via cp.async; fp32 stores)
// stage: A 128x32 (8K) + B 128x32 (8K) = 16KB; x4 = 64KB dynamic.
#define STAGE_BYTES 16384
#define SMEM_TOTAL  (4*STAGE_BYTES)

__global__ void __launch_bounds__(256, 2)
gemm_all(const float* __restrict__ p, const float* __restrict__ c,
         const float* __restrict__ bq, const float* __restrict__ bk,
         const float* __restrict__ bv, const float* __restrict__ bo,
         float* __restrict__ out, int phase)
{
  extern __shared__ __align__(128) char smem[];

  const int job = (int)blockIdx.x;
  const float* __restrict__ Xf = nullptr;
  const __half* __restrict__ Wm;
  __half* __restrict__ Yh = nullptr;
  const float* __restrict__ bias;
  size_t mBase; int nBase;
  if (phase == 1){
    Wm = g_Wf[3]; bias = bo;
    mBase = (size_t)(job >> 1) * 128;  nBase = (job & 1) * 128;
  } else if (job < 1024){
    Xf = p;  Wm = g_Wf[0]; Yh = g_Qh; bias = bq;
    mBase = (size_t)(job >> 1) * 128;  nBase = (job & 1) * 128;
  } else {
    const int j = job - 1024;              // 0..4095
    const int sub = j & 3, kv = sub >> 1;  // K-n0,K-n1,V-n0,V-n1 adjacent
    Xf = c;  mBase = (size_t)(j >> 2) * 128;  nBase = (sub & 1) * 128;
    if (kv == 0){ Wm = g_Wf[1]; Yh = g_Kh; bias = bk; }
    else        { Wm = g_Wf[2]; Yh = g_Vh; bias = bv; }
  }

  const int tid  = threadIdx.x;
  const int lane = tid & 31;
  const int warp = tid >> 5;
  const int wm   = warp & 3;        // rows wm*32
  const int wn   = warp >> 2;       // cols wn*64 (0..1)

  __half* sA[4]; __half* sB[4];
#pragma unroll
  for (int s = 0; s < 4; s++){
    char* st = smem + s * STAGE_BYTES;
    sA[s] = reinterpret_cast<__half*>(st);
    sB[s] = reinterpret_cast<__half*>(st + 8192);
  }

  // ---- fill indices (256 threads) ----
  // fp32 A: 1024 float4 slots (128 rows x 8 f4) -> 4/thread, in 2 halves
  // fp16 A: 512 16B chunks -> 2/thread
  // B:      512 16B chunks -> 2/thread
  const int brow0 = tid >> 2,          bc8 = (tid & 3) * 8;
  const int brow1 = (tid + 256) >> 2;

  auto issueAsync = [&](int kk, int s){
    if (phase == 1){
      uint32_t d0 = (uint32_t)__cvta_generic_to_shared(&sA[s][sw_off(brow0, bc8)]);
      uint32_t d1 = (uint32_t)__cvta_generic_to_shared(&sA[s][sw_off(brow1, bc8)]);
      cp_async16(d0, g_WSh + (mBase + brow0)*E_DIM + kk + bc8);
      cp_async16(d1, g_WSh + (mBase + brow1)*E_DIM + kk + bc8);
    }
    uint32_t db0 = (uint32_t)__cvta_generic_to_shared(&sB[s][sw_off(brow0, bc8)]);
    uint32_t db1 = (uint32_t)__cvta_generic_to_shared(&sB[s][sw_off(brow1, bc8)]);
    cp_async16(db0, Wm + (size_t)(nBase + brow0)*E_DIM + kk + bc8);
    cp_async16(db1, Wm + (size_t)(nBase + brow1)*E_DIM + kk + bc8);
    CP_COMMIT();
  };

  float4 ra[2];
  auto loadAh = [&](int kk, int h){
#pragma unroll
    for (int i = 0; i < 2; i++){
      int slot = tid + i*256 + h*512;
      int row = slot >> 3, c4 = slot & 7;
      ra[i] = *reinterpret_cast<const float4*>(Xf + (mBase + row)*E_DIM + kk + c4*4);
    }
  };
  auto storeAh = [&](int s, int h){
#pragma unroll
    for (int i = 0; i < 2; i++){
      int slot = tid + i*256 + h*512;
      int row = slot >> 3, c4 = slot & 7;
      float4 v = ra[i];
      __half2 h0 = __float22half2_rn(make_float2(v.x, v.y));
      __half2 h1 = __float22half2_rn(make_float2(v.z, v.w));
      int o0 = sw_off(row, c4*4);
      *reinterpret_cast<__half2*>(&sA[s][o0])   = h0;
      *reinterpret_cast<__half2*>(&sA[s][o0+2]) = h1;
    }
  };

  float acc[2][8][4];   // [mt][nt][4]
#pragma unroll
  for (int i=0;i<2;i++)
#pragma unroll
    for (int j=0;j<8;j++)
#pragma unroll
      for (int k=0;k<4;k++) acc[i][j][k] = 0.f;

  // prologue: stages 0..2 in flight
#pragma unroll
  for (int cc = 0; cc < 3; cc++){
    issueAsync(cc*32, cc);
    if (phase == 0){
      loadAh(cc*32, 0); storeAh(cc, 0);
      loadAh(cc*32, 1); storeAh(cc, 1);
    }
  }

  for (int kc = 0; kc < 8; kc++){
    const int cur = kc & 3;
    const int left = 7 - kc;
    if (left >= 2) CP_WAIT2(); else if (left == 1) CP_WAIT1(); else CP_WAIT0();
    __syncthreads();

    const int pre = kc + 3;
    const int ps  = pre & 3;
    if (pre < 8){
      issueAsync(pre*32, ps);
      if (phase == 0) loadAh(pre*32, 0);
    }

    // ---- compute ks2=0 ----
    uint32_t Af[2][4], Bf[4][4];
#pragma unroll
    for (int ks2 = 0; ks2 < 2; ks2++){
      const int ks = ks2*16;
#pragma unroll
      for (int mt=0; mt<2; mt++){
        int row = wm*32 + mt*16 + (lane & 7) + ((lane & 8) ? 8 : 0);
        int col = ks + ((lane & 16) ? 8 : 0);
        ldm4((uint32_t)__cvta_generic_to_shared(sA[cur] + sw_off(row, col)), Af[mt]);
      }
#pragma unroll
      for (int bt=0; bt<4; bt++){
        int row = wn*64 + bt*16 + (lane & 7) + ((lane & 8) ? 8 : 0);
        int col = ks + ((lane & 16) ? 8 : 0);
        ldm4((uint32_t)__cvta_generic_to_shared(sB[cur] + sw_off(row, col)), Bf[bt]);
      }
#pragma unroll
      for (int mt=0; mt<2; mt++)
#pragma unroll
        for (int nt=0; nt<8; nt++){
          const int bt = nt >> 1, od = nt & 1;
          mma16816(acc[mt][nt], Af[mt], Bf[bt][od], Bf[bt][2+od]);
        }
      // interleave A staging for the prefetched chunk between ks halves
      if (pre < 8 && phase == 0){
        if (ks2 == 0){ storeAh(ps, 0); loadAh(pre*32, 1); }
        else         { storeAh(ps, 1); }
      }
    }
  }

  // epilogue: +bias; fp16 stores (Q/K/V) or fp32 (final out)
#pragma unroll
  for (int mt=0; mt<2; mt++){
#pragma unroll
    for (int nt=0; nt<8; nt++){
      size_t m = mBase + wm*32 + mt*16 + (lane>>2);
      int    n = nBase + wn*64 + nt*8 + (lane&3)*2;
      float b0 = bias[n], b1 = bias[n+1];
      float* a = acc[mt][nt];
      if (phase == 1){
        *reinterpret_cast<float2*>(out + m*E_DIM + n)     = make_float2(a[0]+b0, a[1]+b1);
        *reinterpret_cast<float2*>(out + (m+8)*E_DIM + n) = make_float2(a[2]+b0, a[3]+b1);
      } else {
        *reinterpret_cast<__half2*>(Yh + m*E_DIM + n)     = __floats2half2_rn(a[0]+b0, a[1]+b1);
        *reinterpret_cast<__half2*>(Yh + (m+8)*E_DIM + n) = __floats2half2_rn(a[2]+b0, a[3]+b1);
      }
    }
  }
}

// ---------------- attention: warp per token, fp32 math on fp16 data ------------
__device__ __forceinline__ float dot8(uint4 a, uint4 b){
  const __half2* ah = reinterpret_cast<const __half2*>(&a);
  const __half2* bh = reinterpret_cast<const __half2*>(&b);
  float s = 0.f;
#pragma unroll
  for (int i = 0; i < 4; i++){
    float2 af = __half22float2(ah[i]);
    float2 bf = __half22float2(bh[i]);
    s += af.x*bf.x + af.y*bf.y;
  }
  return s;
}

__global__ void __launch_bounds__(256)
attn_kernel()
{
  const int gw   = (blockIdx.x * 256 + threadIdx.x) >> 5;  // token id
  const int lane = threadIdx.x & 31;                        // 8 lanes per head

  const uint4* q  = reinterpret_cast<const uint4*>(g_Qh + (size_t)gw*E_DIM);
  const uint4* k0 = reinterpret_cast<const uint4*>(g_Kh + (size_t)(2*gw  )*E_DIM);
  const uint4* k1 = reinterpret_cast<const uint4*>(g_Kh + (size_t)(2*gw+1)*E_DIM);
  const uint4* v0 = reinterpret_cast<const uint4*>(g_Vh + (size_t)(2*gw  )*E_DIM);
  const uint4* v1 = reinterpret_cast<const uint4*>(g_Vh + (size_t)(2*gw+1)*E_DIM);
  uint4*       ws = reinterpret_cast<uint4*>(g_WSh + (size_t)gw*E_DIM);

  uint4 qa = q[lane];
  float s0 = dot8(qa, k0[lane]);
  float s1 = dot8(qa, k1[lane]);

#pragma unroll
  for (int off = 4; off > 0; off >>= 1){            // reduce within 8-lane head group
    s0 += __shfl_xor_sync(0xffffffffu, s0, off);
    s1 += __shfl_xor_sync(0xffffffffu, s1, off);
  }
  s0 *= 0.125f;  s1 *= 0.125f;                       // 1/sqrt(D), D=64
  float mx = fmaxf(s0, s1);
  float e0 = __expf(s0 - mx), e1 = __expf(s1 - mx);
  float inv = 1.0f / (e0 + e1);
  float w0 = e0 * inv, w1 = e1 * inv;

  uint4 va = v0[lane], vb = v1[lane];
  const __half2* vah = reinterpret_cast<const __half2*>(&va);
  const __half2* vbh = reinterpret_cast<const __half2*>(&vb);
  uint4 o;
  __half2* oh = reinterpret_cast<__half2*>(&o);
#pragma unroll
  for (int i = 0; i < 4; i++){
    float2 a = __half22float2(vah[i]);
    float2 b = __half22float2(vbh[i]);
    oh[i] = __floats2half2_rn(w0*a.x + w1*b.x, w0*a.y + w1*b.y);
  }
  ws[lane] = o;
}

// ---------------- launch ----------------
extern "C" void kernel_launch(void* const* d_in, const int* in_sizes, int n_in,
                              void* d_out, int out_size)
{
  const float* p  = (const float*)d_in[0];  // (B,S,A,1,E)  -> [65536,256]
  const float* c  = (const float*)d_in[1];  // (B,S,A,2,E)  -> [131072,256]
  const float* Wq = (const float*)d_in[2];
  const float* bq = (const float*)d_in[3];
  const float* Wk = (const float*)d_in[4];
  const float* bk = (const float*)d_in[5];
  const float* Wv = (const float*)d_in[6];
  const float* bv = (const float*)d_in[7];
  const float* Wo = (const float*)d_in[8];
  const float* bo = (const float*)d_in[9];
  float* out = (float*)d_out;

  cudaFuncSetAttribute(gemm_all, cudaFuncAttributeMaxDynamicSharedMemorySize, SMEM_TOTAL);

  prep_weights<<<256, 256>>>(Wq, Wk, Wv, Wo);
  // merged Q/K/V: 1024 Q jobs + 4096 KV jobs (128x128 tiles)
  gemm_all<<<5120, 256, SMEM_TOTAL>>>(p, c, bq, bk, bv, bo, out, 0);
  attn_kernel<<<MQ/8, 256>>>();
  // out = WS @ Wo^T + bo
  gemm_all<<<1024, 256, SMEM_TOTAL>>>(p, c, bq, bk, bv, bo, out, 1);
}